// round 4
// baseline (speedup 1.0000x reference)
#include <cuda_runtime.h>

#define EPS_BN 1e-5f
#define EPS_RENORM 1e-9f

typedef unsigned long long ull;

// ---------------- problem constants ----------------
#define BATCH 8
#define CH    1024
#define NPTS  2048
#define CQK   128

// ---------------- scratch (no allocations allowed) ----------------
__device__ float g_x1 [BATCH * CH  * NPTS];                 // 64 MiB
__device__ float g_v  [BATCH * CH  * NPTS];                 // 64 MiB
__device__ float g_q  [BATCH * CQK * NPTS];                 // 8 MiB
__device__ float g_k  [BATCH * CQK * NPTS];                 // 8 MiB
__device__ float g_S  [(size_t)BATCH * NPTS * NPTS];        // 128 MiB
__device__ float g_t  [BATCH * CH  * NPTS];                 // 64 MiB
__device__ float g_rd [BATCH * NPTS];                       // reciprocal colsum

// ---------------- tiny PTX helpers ----------------
__device__ __forceinline__ ull pack2(float lo, float hi) {
    ull r;
    asm("mov.b64 %0, {%1, %2};" : "=l"(r)
        : "r"(__float_as_uint(lo)), "r"(__float_as_uint(hi)));
    return r;
}
__device__ __forceinline__ void unpack2(ull v, float& lo, float& hi) {
    unsigned a, b;
    asm("mov.b64 {%0, %1}, %2;" : "=r"(a), "=r"(b) : "l"(v));
    lo = __uint_as_float(a); hi = __uint_as_float(b);
}
__device__ __forceinline__ void ffma2(ull& d, ull a, ull b) {
    asm("fma.rn.f32x2 %0, %1, %2, %0;" : "+l"(d) : "l"(a), "l"(b));
}
__device__ __forceinline__ void cp16(void* smem_dst, const void* gmem_src) {
    unsigned d = (unsigned)__cvta_generic_to_shared(smem_dst);
    asm volatile("cp.async.cg.shared.global [%0], [%1], 16;"
                 :: "r"(d), "l"(gmem_src) : "memory");
}
__device__ __forceinline__ void cp_commit() {
    asm volatile("cp.async.commit_group;" ::: "memory");
}
#define CP_WAIT(n) asm volatile("cp.async.wait_group %0;" :: "n"(n) : "memory")

// ---------------- GEMM ----------------
// C[b] (M x N) = A[b] * B[b],  B stored [K][N] row-major (ldb = N).
// A_KM == false: A stored [M][K] row-major (lda = K)   (weights, V)
// A_KM == true : A stored [K][M] row-major (lda = M)   (Q for Q^T K)
enum { EPI_NONE = 0, EPI_BN_RELU = 1, EPI_SUB_DIV = 2, EPI_BN_RELU_ADD = 3 };

#define BM 128
#define BN 128
#define BK 16
#define TM 8
#define TN 8
#define PAD 4

template<bool A_KM, int EPI>
__global__ void __launch_bounds__(256)
gemm_kernel(const float* __restrict__ A, size_t sA,
            const float* __restrict__ B, size_t sB,
            float* __restrict__ C, size_t sC,
            int M, int N, int K,
            const float* __restrict__ gg, const float* __restrict__ bb,
            const float* __restrict__ mm, const float* __restrict__ vv,
            const float* __restrict__ add, size_t sAdd,
            const float* __restrict__ rdiv)
{
    // A buffer: A_KM -> [BK][BM+PAD] (16*132=2112), else [BM][BK+PAD] (128*20=2560)
    __shared__ float Ash[2][2560];
    __shared__ float Bsh[2][BK * BN];

    const int bz = blockIdx.z;
    const float* Ab = A + (size_t)bz * sA;
    const float* Bb = B + (size_t)bz * sB;
    float*       Cb = C + (size_t)bz * sC;

    const int rowStart = blockIdx.y * BM;
    const int colStart = blockIdx.x * BN;
    const int t  = threadIdx.x;
    const int tx = t & 15;          // 16 thread-cols
    const int ty = t >> 4;          // 16 thread-rows
    const int lda = A_KM ? M : K;
    const int ldb = N;

    ull acc[TM][TN / 2];
#pragma unroll
    for (int i = 0; i < TM; i++)
#pragma unroll
        for (int j = 0; j < TN / 2; j++) acc[i][j] = 0ULL;

    auto do_prefetch = [&](int k0, int s) {
        if (A_KM) {
#pragma unroll
            for (int p = 0; p < 2; p++) {
                int kr = (t >> 5) + p * 8;
                int m4 = (t & 31) * 4;
                cp16(&Ash[s][kr * (BM + PAD) + m4],
                     Ab + (size_t)(k0 + kr) * lda + rowStart + m4);
            }
        } else {
#pragma unroll
            for (int p = 0; p < 2; p++) {
                int r  = (t >> 2) + p * 64;
                int k4 = (t & 3) * 4;
                cp16(&Ash[s][r * (BK + PAD) + k4],
                     Ab + (size_t)(rowStart + r) * lda + k0 + k4);
            }
        }
#pragma unroll
        for (int p = 0; p < 2; p++) {
            int kr = (t >> 5) + p * 8;
            int n4 = (t & 31) * 4;
            cp16(&Bsh[s][kr * BN + n4],
                 Bb + (size_t)(k0 + kr) * ldb + colStart + n4);
        }
        cp_commit();
    };

    const int T = K / BK;
    do_prefetch(0, 0);
    int cur = 0;

    for (int tile = 0; tile < T; tile++) {
        if (tile + 1 < T) {
            do_prefetch((tile + 1) * BK, cur ^ 1);
            CP_WAIT(1);
        } else {
            CP_WAIT(0);
        }
        __syncthreads();

#pragma unroll
        for (int kk = 0; kk < BK; kk++) {
            ull rb[4];
            const ull* bp = (const ull*)&Bsh[cur][kk * BN + tx * TN];
            rb[0] = bp[0]; rb[1] = bp[1]; rb[2] = bp[2]; rb[3] = bp[3];
#pragma unroll
            for (int i = 0; i < TM; i++) {
                float a = A_KM
                    ? Ash[cur][kk * (BM + PAD) + ty * TM + i]
                    : Ash[cur][(ty * TM + i) * (BK + PAD) + kk];
                ull a2 = pack2(a, a);
                ffma2(acc[i][0], a2, rb[0]);
                ffma2(acc[i][1], a2, rb[1]);
                ffma2(acc[i][2], a2, rb[2]);
                ffma2(acc[i][3], a2, rb[3]);
            }
        }
        __syncthreads();
        cur ^= 1;
    }

    // epilogue
#pragma unroll
    for (int i = 0; i < TM; i++) {
        int r = rowStart + ty * TM + i;
        float s = 1.f, o = 0.f;
        if (EPI == EPI_BN_RELU || EPI == EPI_BN_RELU_ADD) {
            float inv = rsqrtf(vv[r] + EPS_BN);
            s = gg[r] * inv;
            o = bb[r] - mm[r] * s;
        }
        size_t base = (size_t)r * N + colStart + tx * TN;
        const float* addb = (EPI == EPI_SUB_DIV || EPI == EPI_BN_RELU_ADD)
                            ? add + (size_t)bz * sAdd : nullptr;
#pragma unroll
        for (int j = 0; j < TN / 2; j++) {
            float lo, hi; unpack2(acc[i][j], lo, hi);
            size_t idx = base + 2 * j;
            if (EPI == EPI_NONE) {
                Cb[idx]     = lo;
                Cb[idx + 1] = hi;
            } else if (EPI == EPI_BN_RELU) {
                Cb[idx]     = fmaxf(lo * s + o, 0.f);
                Cb[idx + 1] = fmaxf(hi * s + o, 0.f);
            } else if (EPI == EPI_SUB_DIV) {
                int c0 = colStart + tx * TN + 2 * j;
                float d0 = rdiv[(size_t)bz * N + c0];
                float d1 = rdiv[(size_t)bz * N + c0 + 1];
                Cb[idx]     = addb[idx]     - lo * d0;
                Cb[idx + 1] = addb[idx + 1] - hi * d1;
            } else { // EPI_BN_RELU_ADD
                Cb[idx]     = addb[idx]     + fmaxf(lo * s + o, 0.f);
                Cb[idx + 1] = addb[idx + 1] + fmaxf(hi * s + o, 0.f);
            }
        }
    }
}

// ---------------- row softmax (in place), one block per row ----------------
__global__ void __launch_bounds__(256)
softmax_kernel(float* __restrict__ S, int N)
{
    __shared__ float buf[NPTS];
    __shared__ float red[8];
    float* p = S + (size_t)blockIdx.x * N;
    int t = threadIdx.x;

    float mx = -3.402823466e38f;
    for (int i = t; i < N; i += 256) { float v = p[i]; buf[i] = v; mx = fmaxf(mx, v); }
#pragma unroll
    for (int o = 16; o > 0; o >>= 1) mx = fmaxf(mx, __shfl_xor_sync(0xffffffffu, mx, o));
    if ((t & 31) == 0) red[t >> 5] = mx;
    __syncthreads();
    float bm = red[0];
#pragma unroll
    for (int i = 1; i < 8; i++) bm = fmaxf(bm, red[i]);
    __syncthreads();

    float sum = 0.f;
    for (int i = t; i < N; i += 256) { float e = __expf(buf[i] - bm); buf[i] = e; sum += e; }
#pragma unroll
    for (int o = 16; o > 0; o >>= 1) sum += __shfl_xor_sync(0xffffffffu, sum, o);
    if ((t & 31) == 0) red[t >> 5] = sum;
    __syncthreads();
    float bs = 0.f;
#pragma unroll
    for (int i = 0; i < 8; i++) bs += red[i];
    float inv = 1.0f / bs;
    for (int i = t; i < N; i += 256) p[i] = buf[i] * inv;
}

// ---------------- column sums -> reciprocal of (eps + colsum) ----------------
__global__ void __launch_bounds__(256)
colsum_kernel(const float* __restrict__ S, float* __restrict__ rdiv, int N)
{
    int idx = blockIdx.x * 256 + threadIdx.x;   // 0 .. BATCH*N
    int b = idx / N, m = idx - b * N;
    const float* p = S + (size_t)b * N * N + m;
    float s[8] = {0.f, 0.f, 0.f, 0.f, 0.f, 0.f, 0.f, 0.f};
    for (int n = 0; n < N; n += 8) {
#pragma unroll
        for (int u = 0; u < 8; u++) s[u] += p[(size_t)(n + u) * N];
    }
    float tot = ((s[0] + s[1]) + (s[2] + s[3])) + ((s[4] + s[5]) + (s[6] + s[7]));
    rdiv[idx] = 1.0f / (EPS_RENORM + tot);
}

// ---------------- launch ----------------
extern "C" void kernel_launch(void* const* d_in, const int* in_sizes, int n_in,
                              void* d_out, int out_size)
{
    (void)in_sizes; (void)n_in; (void)out_size;
    const float* x  = (const float*)d_in[0];
    const float *W1 = (const float*)d_in[1],  *g1 = (const float*)d_in[2],
                *b1 = (const float*)d_in[3],  *m1 = (const float*)d_in[4],
                *v1 = (const float*)d_in[5];
    const float *W2 = (const float*)d_in[6],  *g2 = (const float*)d_in[7],
                *b2 = (const float*)d_in[8],  *m2 = (const float*)d_in[9],
                *v2 = (const float*)d_in[10];
    const float *W3 = (const float*)d_in[11], *g3 = (const float*)d_in[12],
                *b3 = (const float*)d_in[13], *m3 = (const float*)d_in[14],
                *v3 = (const float*)d_in[15];
    const float *W4 = (const float*)d_in[16], *g4 = (const float*)d_in[17],
                *b4 = (const float*)d_in[18], *m4 = (const float*)d_in[19],
                *v4 = (const float*)d_in[20];
    const float *W5 = (const float*)d_in[21], *g5 = (const float*)d_in[22],
                *b5 = (const float*)d_in[23], *m5 = (const float*)d_in[24],
                *v5 = (const float*)d_in[25];
    float* out = (float*)d_out;

    float *x1, *vb, *qb, *kb, *Sb, *tb, *rd;
    cudaGetSymbolAddress((void**)&x1, g_x1);
    cudaGetSymbolAddress((void**)&vb, g_v);
    cudaGetSymbolAddress((void**)&qb, g_q);
    cudaGetSymbolAddress((void**)&kb, g_k);
    cudaGetSymbolAddress((void**)&Sb, g_S);
    cudaGetSymbolAddress((void**)&tb, g_t);
    cudaGetSymbolAddress((void**)&rd, g_rd);

    const size_t sX  = (size_t)CH  * NPTS;
    const size_t sQK = (size_t)CQK * NPTS;
    const size_t sS  = (size_t)NPTS * NPTS;
    dim3 thr(256);

    // 1) x1 = relu(bn1(W1 @ x))
    gemm_kernel<false, EPI_BN_RELU><<<dim3(NPTS/BN, CH/BM, BATCH), thr>>>(
        W1, 0, x, sX, x1, sX, CH, NPTS, CH, g1, b1, m1, v1, nullptr, 0, nullptr);
    // 2) v = relu(bn2(W2 @ x1))
    gemm_kernel<false, EPI_BN_RELU><<<dim3(NPTS/BN, CH/BM, BATCH), thr>>>(
        W2, 0, x1, sX, vb, sX, CH, NPTS, CH, g2, b2, m2, v2, nullptr, 0, nullptr);
    // 3) q, 4) k
    gemm_kernel<false, EPI_BN_RELU><<<dim3(NPTS/BN, CQK/BM, BATCH), thr>>>(
        W3, 0, x1, sX, qb, sQK, CQK, NPTS, CH, g3, b3, m3, v3, nullptr, 0, nullptr);
    gemm_kernel<false, EPI_BN_RELU><<<dim3(NPTS/BN, CQK/BM, BATCH), thr>>>(
        W4, 0, x1, sX, kb, sQK, CQK, NPTS, CH, g4, b4, m4, v4, nullptr, 0, nullptr);
    // 5) scores = q^T k   (A stored [K=128][M=2048])
    gemm_kernel<true, EPI_NONE><<<dim3(NPTS/BN, NPTS/BM, BATCH), thr>>>(
        qb, sQK, kb, sQK, Sb, sS, NPTS, NPTS, CQK,
        nullptr, nullptr, nullptr, nullptr, nullptr, 0, nullptr);
    // 6) row softmax in place
    softmax_kernel<<<BATCH * NPTS, 256>>>(Sb, NPTS);
    // 7) reciprocal column-sum (renorm divisor)
    colsum_kernel<<<BATCH * NPTS / 256, 256>>>(Sb, rd, NPTS);
    // 8) t = x1 - (v @ S) * rdiv[col]
    gemm_kernel<false, EPI_SUB_DIV><<<dim3(NPTS/BN, CH/BM, BATCH), thr>>>(
        vb, sX, Sb, sS, tb, sX, CH, NPTS, NPTS,
        nullptr, nullptr, nullptr, nullptr, x1, sX, rd);
    // 9) out = x1 + relu(bn5(W5 @ t))
    gemm_kernel<false, EPI_BN_RELU_ADD><<<dim3(NPTS/BN, CH/BM, BATCH), thr>>>(
        W5, 0, tb, sX, out, sX, CH, NPTS, CH, g5, b5, m5, v5, x1, sX, nullptr);
}